// round 2
// baseline (speedup 1.0000x reference)
#include <cuda_runtime.h>
#include <math_constants.h>

#define BATCH 4096
#define DIM 256
#define NEG_INF (-CUDART_INF_F)

// Static scratch (no allocations allowed).
__device__ float g_an[BATCH * DIM];
__device__ float g_p0[BATCH * DIM];
__device__ float g_p1[BATCH * DIM];
__device__ float g_posdot[2][BATCH];
__device__ unsigned g_maxbits[2][BATCH];
__device__ float g_partial[32];

// Order-preserving float <-> uint encoding for atomicMax on floats.
__device__ __forceinline__ unsigned enc_f(float f) {
    unsigned u = __float_as_uint(f);
    return (u & 0x80000000u) ? ~u : (u | 0x80000000u);
}
__device__ __forceinline__ float dec_f(unsigned u) {
    u = (u & 0x80000000u) ? (u & 0x7FFFFFFFu) : ~u;
    return __uint_as_float(u);
}

// ---------------------------------------------------------------------------
// Kernel 1: normalize anchor rows and both positive views; init max buffers.
// 64 threads per row, float4 per thread.
// ---------------------------------------------------------------------------
__global__ void normalize_kernel(const float* __restrict__ anchor,
                                 const float* __restrict__ positive) {
    int bid = blockIdx.x;
    int tid = threadIdx.x;
    const float* src;
    float* dst;
    if (bid < BATCH) {
        src = anchor + (size_t)bid * DIM;
        dst = g_an + (size_t)bid * DIM;
        if (tid == 0) {
            g_maxbits[0][bid] = 0u;
            g_maxbits[1][bid] = 0u;
        }
    } else {
        int m = bid - BATCH;           // m = i*2 + v (matches [B,P,D] layout)
        int i = m >> 1;
        int v = m & 1;
        src = positive + (size_t)m * DIM;
        dst = (v == 0 ? g_p0 : g_p1) + (size_t)i * DIM;
    }
    float4 x = ((const float4*)src)[tid];
    float s = x.x * x.x + x.y * x.y + x.z * x.z + x.w * x.w;
#pragma unroll
    for (int o = 16; o; o >>= 1) s += __shfl_down_sync(0xffffffffu, s, o);
    __shared__ float ws[2];
    if ((tid & 31) == 0) ws[tid >> 5] = s;
    __syncthreads();
    float tot = ws[0] + ws[1];
    float inv = 1.0f / fmaxf(sqrtf(tot), 1e-12f);
    x.x *= inv; x.y *= inv; x.z *= inv; x.w *= inv;
    ((float4*)dst)[tid] = x;
}

// ---------------------------------------------------------------------------
// Kernel 2: positive dot products (a_i . p_{i,v}); one warp per (i, v).
// ---------------------------------------------------------------------------
__global__ void posdot_kernel() {
    int w = (blockIdx.x * blockDim.x + threadIdx.x) >> 5;
    int lane = threadIdx.x & 31;
    int i = w >> 1;
    int v = w & 1;
    const float* a = g_an + (size_t)i * DIM;
    const float* p = (v == 0 ? g_p0 : g_p1) + (size_t)i * DIM;
    float s = 0.f;
#pragma unroll
    for (int k = 0; k < DIM / 32; k++) s += a[lane + 32 * k] * p[lane + 32 * k];
#pragma unroll
    for (int o = 16; o; o >>= 1) s += __shfl_down_sync(0xffffffffu, s, o);
    if (lane == 0) g_posdot[v][i] = s;
}

// ---------------------------------------------------------------------------
// Kernel 3: fused GEMM + masked row-max.
// A = g_an [4096,256]. Column source selected by blockIdx.x / 64:
//   src 0: g_an (a-columns, feed BOTH views), src 1: g_p0, src 2: g_p1.
// 64x64 block tile, 256 threads, 4x4 micro-tile, K tiled by 16.
// Epilogue: masked max per row -> atomicMax on encoded dot.
// ---------------------------------------------------------------------------
__global__ __launch_bounds__(256) void gemm_max_kernel(const int* __restrict__ labels) {
    int ct = blockIdx.x;               // 0..191
    int rt = blockIdx.y;               // 0..63
    int src = ct >> 6;                 // 0,1,2
    int col0 = (ct & 63) * 64;
    int row0 = rt * 64;
    const float* Bmat = (src == 0) ? g_an : (src == 1 ? g_p0 : g_p1);

    __shared__ float As[16][64];
    __shared__ float Bs[16][64];
    __shared__ int labR[64];
    __shared__ int labC[64];
    __shared__ float red[64][16];

    int tid = threadIdx.x;
    if (tid < 64) labR[tid] = labels[row0 + tid];
    else if (tid < 128) labC[tid - 64] = labels[col0 + (tid - 64)];

    float acc[4][4];
#pragma unroll
    for (int i = 0; i < 4; i++)
#pragma unroll
        for (int j = 0; j < 4; j++) acc[i][j] = 0.f;

    int lr = tid >> 2;                 // 0..63  (row within tile to load)
    int lk = (tid & 3) << 2;           // 0,4,8,12
    const float* Ap = g_an + (size_t)(row0 + lr) * DIM + lk;
    const float* Bp = Bmat + (size_t)(col0 + lr) * DIM + lk;

    int rb = (tid >> 4) << 2;          // my 4 rows
    int cb = (tid & 15) << 2;          // my 4 cols

    for (int kt = 0; kt < DIM; kt += 16) {
        float4 a4 = *(const float4*)(Ap + kt);
        float4 b4 = *(const float4*)(Bp + kt);
        __syncthreads();
        As[lk + 0][lr] = a4.x; As[lk + 1][lr] = a4.y;
        As[lk + 2][lr] = a4.z; As[lk + 3][lr] = a4.w;
        Bs[lk + 0][lr] = b4.x; Bs[lk + 1][lr] = b4.y;
        Bs[lk + 2][lr] = b4.z; Bs[lk + 3][lr] = b4.w;
        __syncthreads();
#pragma unroll
        for (int kk = 0; kk < 16; kk++) {
            float4 ra = *(const float4*)&As[kk][rb];
            float4 rc = *(const float4*)&Bs[kk][cb];
            acc[0][0] += ra.x * rc.x; acc[0][1] += ra.x * rc.y;
            acc[0][2] += ra.x * rc.z; acc[0][3] += ra.x * rc.w;
            acc[1][0] += ra.y * rc.x; acc[1][1] += ra.y * rc.y;
            acc[1][2] += ra.y * rc.z; acc[1][3] += ra.y * rc.w;
            acc[2][0] += ra.z * rc.x; acc[2][1] += ra.z * rc.y;
            acc[2][2] += ra.z * rc.z; acc[2][3] += ra.z * rc.w;
            acc[3][0] += ra.w * rc.x; acc[3][1] += ra.w * rc.y;
            acc[3][2] += ra.w * rc.z; acc[3][3] += ra.w * rc.w;
        }
    }

    // Epilogue: label-masked max over my 4 columns, per row.
    int cl0 = labC[cb + 0], cl1 = labC[cb + 1], cl2 = labC[cb + 2], cl3 = labC[cb + 3];
#pragma unroll
    for (int i = 0; i < 4; i++) {
        int rl = labR[rb + i];
        float mm = NEG_INF;
        if (cl0 != rl) mm = fmaxf(mm, acc[i][0]);
        if (cl1 != rl) mm = fmaxf(mm, acc[i][1]);
        if (cl2 != rl) mm = fmaxf(mm, acc[i][2]);
        if (cl3 != rl) mm = fmaxf(mm, acc[i][3]);
        red[rb + i][tid & 15] = mm;
    }
    __syncthreads();
    if (tid < 64) {
        float mm = NEG_INF;
#pragma unroll
        for (int t = 0; t < 16; t++) mm = fmaxf(mm, red[tid][t]);
        unsigned e = enc_f(mm);
        if (src == 0) {
            atomicMax(&g_maxbits[0][row0 + tid], e);
            atomicMax(&g_maxbits[1][row0 + tid], e);
        } else {
            atomicMax(&g_maxbits[src - 1][row0 + tid], e);
        }
    }
}

// ---------------------------------------------------------------------------
// Kernel 4: per-element triplet loss + deterministic block partial sums.
// ---------------------------------------------------------------------------
__global__ void loss_kernel() {
    int idx = blockIdx.x * 256 + threadIdx.x;   // 0..8191
    int v = idx >> 12;
    int i = idx & (BATCH - 1);
    float pd = g_posdot[v][i];
    float nd = dec_f(g_maxbits[v][i]);
    float pos = sqrtf(fmaxf(2.0f - 2.0f * pd, 1e-12f));
    float neg = sqrtf(fmaxf(2.0f - 2.0f * nd, 1e-12f));
    float loss = fmaxf(pos - neg + 1.0f, 0.0f);
    __shared__ float sm[256];
    sm[threadIdx.x] = loss;
    __syncthreads();
    for (int s = 128; s; s >>= 1) {
        if (threadIdx.x < s) sm[threadIdx.x] += sm[threadIdx.x + s];
        __syncthreads();
    }
    if (threadIdx.x == 0) g_partial[blockIdx.x] = sm[0];
}

__global__ void final_kernel(float* __restrict__ out) {
    if (threadIdx.x == 0) {
        float s = 0.f;
#pragma unroll
        for (int i = 0; i < 32; i++) s += g_partial[i];
        out[0] = s * (1.0f / 8192.0f);
    }
}

// ---------------------------------------------------------------------------
extern "C" void kernel_launch(void* const* d_in, const int* in_sizes, int n_in,
                              void* d_out, int out_size) {
    const float* anchor = (const float*)d_in[0];
    const float* positive = (const float*)d_in[1];
    const int* labels = (const int*)d_in[2];

    normalize_kernel<<<3 * BATCH, 64>>>(anchor, positive);
    posdot_kernel<<<(2 * BATCH * 32) / 256, 256>>>();
    gemm_max_kernel<<<dim3(192, 64), 256>>>(labels);
    loss_kernel<<<32, 256>>>();
    final_kernel<<<1, 32>>>((float*)d_out);
}

// round 6
// speedup vs baseline: 10.4327x; 10.4327x over previous
#include <cuda_runtime.h>
#include <cuda_bf16.h>
#include <math_constants.h>
#include <cstdint>

#define BATCH 4096
#define DIM 256
#define NEG_INF (-CUDART_INF_F)

// ---------------- static scratch ----------------
__device__ float g_af[BATCH * DIM];            // normalized fp32
__device__ float g_p0f[BATCH * DIM];
__device__ float g_p1f[BATCH * DIM];
__device__ __nv_bfloat16 g_ab[BATCH * DIM];    // normalized bf16
__device__ __nv_bfloat16 g_p0b[BATCH * DIM];
__device__ __nv_bfloat16 g_p1b[BATCH * DIM];
__device__ float g_posdot[2][BATCH];
__device__ unsigned g_maxbits[2][BATCH];
__device__ float g_partial[32];

// ---------------- helpers ----------------
__device__ __forceinline__ unsigned enc_f(float f) {
    unsigned u = __float_as_uint(f);
    return (u & 0x80000000u) ? ~u : (u | 0x80000000u);
}
__device__ __forceinline__ float dec_f(unsigned u) {
    u = (u & 0x80000000u) ? (u & 0x7FFFFFFFu) : ~u;
    return __uint_as_float(u);
}
__device__ __forceinline__ uint32_t smem_u32(const void* p) {
    uint32_t a;
    asm("{ .reg .u64 t; cvta.to.shared.u64 t, %1; cvt.u32.u64 %0, t; }" : "=r"(a) : "l"(p));
    return a;
}
__device__ __forceinline__ void cp_async16(uint32_t dst, const void* src) {
    asm volatile("cp.async.cg.shared.global [%0], [%1], 16;" :: "r"(dst), "l"(src) : "memory");
}
#define CP_COMMIT() asm volatile("cp.async.commit_group;" ::: "memory")
#define CP_WAIT1()  asm volatile("cp.async.wait_group 1;" ::: "memory")

__device__ __forceinline__ void ldsm_x4(uint32_t& r0, uint32_t& r1, uint32_t& r2, uint32_t& r3,
                                        uint32_t addr) {
    asm volatile("ldmatrix.sync.aligned.m8n8.x4.shared.b16 {%0,%1,%2,%3}, [%4];"
                 : "=r"(r0), "=r"(r1), "=r"(r2), "=r"(r3) : "r"(addr));
}
__device__ __forceinline__ void mma16816(float* c, const uint32_t* a, const uint32_t* b) {
    asm volatile(
        "mma.sync.aligned.m16n8k16.row.col.f32.bf16.bf16.f32 "
        "{%0,%1,%2,%3}, {%4,%5,%6,%7}, {%8,%9}, {%0,%1,%2,%3};"
        : "+f"(c[0]), "+f"(c[1]), "+f"(c[2]), "+f"(c[3])
        : "r"(a[0]), "r"(a[1]), "r"(a[2]), "r"(a[3]), "r"(b[0]), "r"(b[1]));
}

// ---------------- kernel 1: normalize, write fp32 + bf16 ----------------
__global__ void normalize_kernel(const float* __restrict__ anchor,
                                 const float* __restrict__ positive) {
    int bid = blockIdx.x;
    int tid = threadIdx.x;
    const float* src;
    float* dstf;
    __nv_bfloat16* dstb;
    if (bid < BATCH) {
        src = anchor + (size_t)bid * DIM;
        dstf = g_af + (size_t)bid * DIM;
        dstb = g_ab + (size_t)bid * DIM;
        if (tid == 0) { g_maxbits[0][bid] = 0u; g_maxbits[1][bid] = 0u; }
    } else {
        int m = bid - BATCH;
        int i = m >> 1;
        int v = m & 1;
        src = positive + (size_t)m * DIM;
        dstf = (v == 0 ? g_p0f : g_p1f) + (size_t)i * DIM;
        dstb = (v == 0 ? g_p0b : g_p1b) + (size_t)i * DIM;
    }
    float4 x = ((const float4*)src)[tid];
    float s = x.x * x.x + x.y * x.y + x.z * x.z + x.w * x.w;
#pragma unroll
    for (int o = 16; o; o >>= 1) s += __shfl_down_sync(0xffffffffu, s, o);
    __shared__ float ws[2];
    if ((tid & 31) == 0) ws[tid >> 5] = s;
    __syncthreads();
    float inv = 1.0f / fmaxf(sqrtf(ws[0] + ws[1]), 1e-12f);
    x.x *= inv; x.y *= inv; x.z *= inv; x.w *= inv;
    ((float4*)dstf)[tid] = x;
    __nv_bfloat162 lo = __floats2bfloat162_rn(x.x, x.y);
    __nv_bfloat162 hi = __floats2bfloat162_rn(x.z, x.w);
    uint2 pk;
    pk.x = *(uint32_t*)&lo; pk.y = *(uint32_t*)&hi;
    ((uint2*)dstb)[tid] = pk;
}

// ---------------- kernel 2: positive dots (fp32) ----------------
__global__ void posdot_kernel() {
    int w = (blockIdx.x * blockDim.x + threadIdx.x) >> 5;
    int lane = threadIdx.x & 31;
    int i = w >> 1, v = w & 1;
    const float* a = g_af + (size_t)i * DIM;
    const float* p = (v == 0 ? g_p0f : g_p1f) + (size_t)i * DIM;
    float s = 0.f;
#pragma unroll
    for (int k = 0; k < DIM / 32; k++) s += a[lane + 32 * k] * p[lane + 32 * k];
#pragma unroll
    for (int o = 16; o; o >>= 1) s += __shfl_down_sync(0xffffffffu, s, o);
    if (lane == 0) g_posdot[v][i] = s;
}

// ---------------- kernel 3: bf16 mma.sync GEMM + masked max ----------------
// CTA tile 128x128, 8 warps (2 m x 4 n), warp tile 64x32, K chunks of 64,
// 2-stage cp.async pipeline. SMEM rows are 128B with kb^(row&7) swizzle.
#define TILE 128
#define KC 64
#define CHUNK_BYTES (128 * 128)        // per matrix per stage = 16384
#define SM_LABC 0                      // 512 B
#define SM_LABR 512                    // 512 B
#define SM_MAX  1024                   // 512 B
#define SM_BUF  2048
#define SM_TOTAL (SM_BUF + 4 * CHUNK_BYTES)   // 67584

__global__ __launch_bounds__(256, 2) void gemm_max_kernel(const int* __restrict__ labels) {
    extern __shared__ char smem[];
    uint32_t smem_base = smem_u32(smem);
    int tid = threadIdx.x;
    int wid = tid >> 5, lane = tid & 31;
    int wm = wid >> 2;                 // 0..1  m-offset wm*64
    int wn = wid & 3;                  // 0..3  n-offset wn*32

    int ct = blockIdx.x;               // 0..95
    int rt = blockIdx.y;               // 0..31
    int src = ct >> 5;                 // 0,1,2
    int colbase = (ct & 31) * TILE;
    int row0 = rt * TILE;
    const __nv_bfloat16* Bmat = (src == 0) ? g_ab : (src == 1 ? g_p0b : g_p1b);

    if (tid < TILE) {
        *(int*)(smem + SM_LABC + tid * 4) = labels[colbase + tid];
        *(int*)(smem + SM_LABR + tid * 4) = labels[row0 + tid];
        *(unsigned*)(smem + SM_MAX + tid * 4) = 0u;
    }

    const char* gA = (const char*)(g_ab + (size_t)row0 * DIM);
    const char* gB = (const char*)(Bmat + (size_t)colbase * DIM);

    // per-thread load coords: 8 cp.async per chunk (4 A + 4 B)
    int lrow = tid >> 1;                       // base id = tid + i*256 -> row=id>>3 ... recompute inline
    (void)lrow;

    auto load_stage = [&](int s, int kc) {
        uint32_t abase = smem_base + SM_BUF + s * (2 * CHUNK_BYTES);
        uint32_t bbase = abase + CHUNK_BYTES;
#pragma unroll
        for (int i = 0; i < 4; i++) {
            int id = tid + i * 256;
            int row = id >> 3, kb = id & 7;
            uint32_t off = row * 128 + ((kb ^ (row & 7)) << 4);
            cp_async16(abase + off, gA + row * 512 + kc * 128 + kb * 16);
        }
#pragma unroll
        for (int i = 0; i < 4; i++) {
            int id = tid + i * 256;
            int row = id >> 3, kb = id & 7;
            uint32_t off = row * 128 + ((kb ^ (row & 7)) << 4);
            cp_async16(bbase + off, gB + row * 512 + kc * 128 + kb * 16);
        }
    };

    float acc[4][4][4];
#pragma unroll
    for (int i = 0; i < 4; i++)
#pragma unroll
        for (int j = 0; j < 4; j++)
#pragma unroll
            for (int k = 0; k < 4; k++) acc[i][j][k] = 0.f;

    // precomputed fragment address components
    int arow_lo = wm * 64 + (lane & 15);
    int brow_lo = wn * 32 + (lane & 7) + ((lane >> 4) << 3);
    int a_kb_lo = lane >> 4;           // +2*ks
    int b_kb_lo = (lane >> 3) & 1;     // +2*ks

    load_stage(0, 0);
    CP_COMMIT();

#pragma unroll
    for (int kc = 0; kc < 4; kc++) {
        if (kc < 3) load_stage((kc + 1) & 1, kc + 1);
        CP_COMMIT();
        CP_WAIT1();
        __syncthreads();

        uint32_t abase = smem_base + SM_BUF + (kc & 1) * (2 * CHUNK_BYTES);
        uint32_t bbase = abase + CHUNK_BYTES;
#pragma unroll
        for (int ks = 0; ks < 4; ks++) {
            uint32_t a[4][4];
            int akb = 2 * ks + a_kb_lo;
#pragma unroll
            for (int mf = 0; mf < 4; mf++) {
                int row = arow_lo + mf * 16;
                uint32_t addr = abase + row * 128 + ((akb ^ (row & 7)) << 4);
                ldsm_x4(a[mf][0], a[mf][1], a[mf][2], a[mf][3], addr);
            }
            uint32_t b[4][2];
            int bkb = 2 * ks + b_kb_lo;
#pragma unroll
            for (int nf2 = 0; nf2 < 2; nf2++) {
                int row = brow_lo + nf2 * 16;
                uint32_t addr = bbase + row * 128 + ((bkb ^ (row & 7)) << 4);
                uint32_t r0, r1, r2, r3;
                ldsm_x4(r0, r1, r2, r3, addr);
                b[nf2 * 2][0] = r0; b[nf2 * 2][1] = r1;
                b[nf2 * 2 + 1][0] = r2; b[nf2 * 2 + 1][1] = r3;
            }
#pragma unroll
            for (int mf = 0; mf < 4; mf++)
#pragma unroll
                for (int nfi = 0; nfi < 4; nfi++)
                    mma16816(acc[mf][nfi], a[mf], b[nfi]);
        }
        __syncthreads();
    }

    // ---- epilogue: label-masked max, smem reduce, global atomic ----
    int g = lane >> 2, tg = lane & 3;
    const int* labC = (const int*)(smem + SM_LABC);
    const int* labR = (const int*)(smem + SM_LABR);
    unsigned* smax = (unsigned*)(smem + SM_MAX);
#pragma unroll
    for (int mf = 0; mf < 4; mf++) {
#pragma unroll
        for (int h = 0; h < 2; h++) {
            int row = wm * 64 + mf * 16 + g + h * 8;
            int rl = labR[row];
            float m = NEG_INF;
#pragma unroll
            for (int nfi = 0; nfi < 4; nfi++) {
                int col = wn * 32 + nfi * 8 + 2 * tg;
                float c0 = acc[mf][nfi][h * 2 + 0];
                float c1 = acc[mf][nfi][h * 2 + 1];
                if (labC[col] != rl)     m = fmaxf(m, c0);
                if (labC[col + 1] != rl) m = fmaxf(m, c1);
            }
            atomicMax(&smax[row], enc_f(m));
        }
    }
    __syncthreads();
    if (tid < TILE) {
        unsigned e = smax[tid];
        int grow = row0 + tid;
        if (src == 0) {
            atomicMax(&g_maxbits[0][grow], e);
            atomicMax(&g_maxbits[1][grow], e);
        } else {
            atomicMax(&g_maxbits[src - 1][grow], e);
        }
    }
}

// ---------------- kernel 4/5: loss + reduce ----------------
__global__ void loss_kernel() {
    int idx = blockIdx.x * 256 + threadIdx.x;   // 0..8191
    int v = idx >> 12;
    int i = idx & (BATCH - 1);
    float pd = g_posdot[v][i];
    float nd = dec_f(g_maxbits[v][i]);
    float pos = sqrtf(fmaxf(2.0f - 2.0f * pd, 1e-12f));
    float neg = sqrtf(fmaxf(2.0f - 2.0f * nd, 1e-12f));
    float loss = fmaxf(pos - neg + 1.0f, 0.0f);
    __shared__ float sm[256];
    sm[threadIdx.x] = loss;
    __syncthreads();
    for (int s = 128; s; s >>= 1) {
        if (threadIdx.x < s) sm[threadIdx.x] += sm[threadIdx.x + s];
        __syncthreads();
    }
    if (threadIdx.x == 0) g_partial[blockIdx.x] = sm[0];
}

__global__ void final_kernel(float* __restrict__ out) {
    if (threadIdx.x == 0) {
        float s = 0.f;
#pragma unroll
        for (int i = 0; i < 32; i++) s += g_partial[i];
        out[0] = s * (1.0f / 8192.0f);
    }
}

// ---------------------------------------------------------------------------
extern "C" void kernel_launch(void* const* d_in, const int* in_sizes, int n_in,
                              void* d_out, int out_size) {
    const float* anchor = (const float*)d_in[0];
    const float* positive = (const float*)d_in[1];
    const int* labels = (const int*)d_in[2];

    cudaFuncSetAttribute(gemm_max_kernel, cudaFuncAttributeMaxDynamicSharedMemorySize, SM_TOTAL);

    normalize_kernel<<<3 * BATCH, 64>>>(anchor, positive);
    posdot_kernel<<<(2 * BATCH * 32) / 256, 256>>>();
    gemm_max_kernel<<<dim3(96, 32), 256, SM_TOTAL>>>(labels);
    loss_kernel<<<32, 256>>>();
    final_kernel<<<1, 32>>>((float*)d_out);
}

// round 8
// speedup vs baseline: 11.4597x; 1.0984x over previous
#include <cuda_runtime.h>
#include <cuda_bf16.h>
#include <math_constants.h>
#include <cstdint>

#define BATCH 4096
#define DIM 256
#define NEG_INF (-CUDART_INF_F)

// ---------------- static scratch ----------------
__device__ __nv_bfloat16 g_ab[BATCH * DIM];    // normalized bf16
__device__ __nv_bfloat16 g_p0b[BATCH * DIM];
__device__ __nv_bfloat16 g_p1b[BATCH * DIM];
__device__ float g_posdot[2][BATCH];
__device__ unsigned g_maxbits[2][BATCH];

// ---------------- helpers ----------------
__device__ __forceinline__ unsigned enc_f(float f) {
    unsigned u = __float_as_uint(f);
    return (u & 0x80000000u) ? ~u : (u | 0x80000000u);
}
__device__ __forceinline__ float dec_f(unsigned u) {
    u = (u & 0x80000000u) ? (u & 0x7FFFFFFFu) : ~u;
    return __uint_as_float(u);
}
__device__ __forceinline__ uint32_t smem_u32(const void* p) {
    uint32_t a;
    asm("{ .reg .u64 t; cvta.to.shared.u64 t, %1; cvt.u32.u64 %0, t; }" : "=r"(a) : "l"(p));
    return a;
}
__device__ __forceinline__ void cp_async16(uint32_t dst, const void* src) {
    asm volatile("cp.async.cg.shared.global [%0], [%1], 16;" :: "r"(dst), "l"(src) : "memory");
}
#define CP_COMMIT() asm volatile("cp.async.commit_group;" ::: "memory")
#define CP_WAIT1()  asm volatile("cp.async.wait_group 1;" ::: "memory")

__device__ __forceinline__ void ldsm_x4(uint32_t& r0, uint32_t& r1, uint32_t& r2, uint32_t& r3,
                                        uint32_t addr) {
    asm volatile("ldmatrix.sync.aligned.m8n8.x4.shared.b16 {%0,%1,%2,%3}, [%4];"
                 : "=r"(r0), "=r"(r1), "=r"(r2), "=r"(r3) : "r"(addr));
}
__device__ __forceinline__ void mma16816(float* c, const uint32_t* a, const uint32_t* b) {
    asm volatile(
        "mma.sync.aligned.m16n8k16.row.col.f32.bf16.bf16.f32 "
        "{%0,%1,%2,%3}, {%4,%5,%6,%7}, {%8,%9}, {%0,%1,%2,%3};"
        : "+f"(c[0]), "+f"(c[1]), "+f"(c[2]), "+f"(c[3])
        : "r"(a[0]), "r"(a[1]), "r"(a[2]), "r"(a[3]), "r"(b[0]), "r"(b[1]));
}

// ---------------- kernel 1: fused normalize + positive dots ----------------
// One block of 64 threads per batch row: loads a, p0, p1; computes 3 norms and
// 2 cross dots; writes bf16 normalized rows, posdot, and inits maxbits.
__global__ void norm_kernel(const float* __restrict__ anchor,
                            const float* __restrict__ positive) {
    int i = blockIdx.x;
    int tid = threadIdx.x;                       // 0..63
    float4 a  = ((const float4*)(anchor  + (size_t)i * DIM))[tid];
    float4 p0 = ((const float4*)(positive + (size_t)i * 2 * DIM))[tid];
    float4 p1 = ((const float4*)(positive + (size_t)i * 2 * DIM + DIM))[tid];

    float s[5];
    s[0] = a.x * a.x + a.y * a.y + a.z * a.z + a.w * a.w;
    s[1] = p0.x * p0.x + p0.y * p0.y + p0.z * p0.z + p0.w * p0.w;
    s[2] = p1.x * p1.x + p1.y * p1.y + p1.z * p1.z + p1.w * p1.w;
    s[3] = a.x * p0.x + a.y * p0.y + a.z * p0.z + a.w * p0.w;
    s[4] = a.x * p1.x + a.y * p1.y + a.z * p1.z + a.w * p1.w;
#pragma unroll
    for (int k = 0; k < 5; k++)
#pragma unroll
        for (int o = 16; o; o >>= 1) s[k] += __shfl_down_sync(0xffffffffu, s[k], o);
    __shared__ float ws[2][5];
    if ((tid & 31) == 0)
#pragma unroll
        for (int k = 0; k < 5; k++) ws[tid >> 5][k] = s[k];
    __syncthreads();
    float na = ws[0][0] + ws[1][0];
    float n0 = ws[0][1] + ws[1][1];
    float n1 = ws[0][2] + ws[1][2];
    float d0 = ws[0][3] + ws[1][3];
    float d1 = ws[0][4] + ws[1][4];
    float ia = 1.0f / fmaxf(sqrtf(na), 1e-12f);
    float i0 = 1.0f / fmaxf(sqrtf(n0), 1e-12f);
    float i1 = 1.0f / fmaxf(sqrtf(n1), 1e-12f);

    if (tid == 0) {
        g_posdot[0][i] = d0 * ia * i0;
        g_posdot[1][i] = d1 * ia * i1;
        g_maxbits[0][i] = 0u;
        g_maxbits[1][i] = 0u;
    }

    uint2 pk;
    __nv_bfloat162 lo, hi;
    lo = __floats2bfloat162_rn(a.x * ia, a.y * ia);
    hi = __floats2bfloat162_rn(a.z * ia, a.w * ia);
    pk.x = *(uint32_t*)&lo; pk.y = *(uint32_t*)&hi;
    ((uint2*)(g_ab + (size_t)i * DIM))[tid] = pk;
    lo = __floats2bfloat162_rn(p0.x * i0, p0.y * i0);
    hi = __floats2bfloat162_rn(p0.z * i0, p0.w * i0);
    pk.x = *(uint32_t*)&lo; pk.y = *(uint32_t*)&hi;
    ((uint2*)(g_p0b + (size_t)i * DIM))[tid] = pk;
    lo = __floats2bfloat162_rn(p1.x * i1, p1.y * i1);
    hi = __floats2bfloat162_rn(p1.z * i1, p1.w * i1);
    pk.x = *(uint32_t*)&lo; pk.y = *(uint32_t*)&hi;
    ((uint2*)(g_p1b + (size_t)i * DIM))[tid] = pk;
}

// ---------------- kernel 2: bf16 mma.sync GEMM + masked max ----------------
// CTA tile 128x128, 8 warps (2 m x 4 n), warp tile 64x32, K chunks of 64,
// 2-stage cp.async pipeline, kb^(row&7) swizzle.
// Grid (32, 32, 3): x = coltile, y = rowtile, z = src.
// src 0 (a . a) is symmetric: only coltile >= rowtile computed; off-diagonal
// tiles also fold per-column maxima (mirror entries).
#define TILE 128
#define CHUNK_BYTES (128 * 128)
#define SM_LABC 0
#define SM_LABR 512
#define SM_MAXR 1024
#define SM_MAXC 1536
#define SM_BUF  2048
#define SM_TOTAL (SM_BUF + 4 * CHUNK_BYTES)   // 67584

__global__ __launch_bounds__(256, 2) void gemm_max_kernel(const int* __restrict__ labels) {
    int ctile = blockIdx.x, rtile = blockIdx.y, src = blockIdx.z;
    if (src == 0 && ctile < rtile) return;          // symmetric skip
    bool colfold = (src == 0) && (ctile > rtile);

    extern __shared__ char smem[];
    uint32_t smem_base = smem_u32(smem);
    int tid = threadIdx.x;
    int wid = tid >> 5, lane = tid & 31;
    int wm = wid >> 2;                 // 0..1
    int wn = wid & 3;                  // 0..3

    int colbase = ctile * TILE;
    int row0 = rtile * TILE;
    const __nv_bfloat16* Bmat = (src == 0) ? g_ab : (src == 1 ? g_p0b : g_p1b);

    if (tid < TILE) {
        *(int*)(smem + SM_LABC + tid * 4) = labels[colbase + tid];
        *(int*)(smem + SM_LABR + tid * 4) = labels[row0 + tid];
        *(unsigned*)(smem + SM_MAXR + tid * 4) = 0u;
        *(unsigned*)(smem + SM_MAXC + tid * 4) = 0u;
    }

    const char* gA = (const char*)(g_ab + (size_t)row0 * DIM);
    const char* gB = (const char*)(Bmat + (size_t)colbase * DIM);

    auto load_stage = [&](int s, int kc) {
        uint32_t abase = smem_base + SM_BUF + s * (2 * CHUNK_BYTES);
        uint32_t bbase = abase + CHUNK_BYTES;
#pragma unroll
        for (int i = 0; i < 4; i++) {
            int id = tid + i * 256;
            int row = id >> 3, kb = id & 7;
            uint32_t off = row * 128 + ((kb ^ (row & 7)) << 4);
            cp_async16(abase + off, gA + row * 512 + kc * 128 + kb * 16);
        }
#pragma unroll
        for (int i = 0; i < 4; i++) {
            int id = tid + i * 256;
            int row = id >> 3, kb = id & 7;
            uint32_t off = row * 128 + ((kb ^ (row & 7)) << 4);
            cp_async16(bbase + off, gB + row * 512 + kc * 128 + kb * 16);
        }
    };

    float acc[4][4][4];
#pragma unroll
    for (int i = 0; i < 4; i++)
#pragma unroll
        for (int j = 0; j < 4; j++)
#pragma unroll
            for (int k = 0; k < 4; k++) acc[i][j][k] = 0.f;

    int arow_lo = wm * 64 + (lane & 15);
    int brow_lo = wn * 32 + (lane & 7) + ((lane >> 4) << 3);
    int a_kb_lo = lane >> 4;
    int b_kb_lo = (lane >> 3) & 1;

    load_stage(0, 0);
    CP_COMMIT();

#pragma unroll
    for (int kc = 0; kc < 4; kc++) {
        if (kc < 3) load_stage((kc + 1) & 1, kc + 1);
        CP_COMMIT();
        CP_WAIT1();
        __syncthreads();

        uint32_t abase = smem_base + SM_BUF + (kc & 1) * (2 * CHUNK_BYTES);
        uint32_t bbase = abase + CHUNK_BYTES;
#pragma unroll
        for (int ks = 0; ks < 4; ks++) {
            uint32_t a[4][4];
            int akb = 2 * ks + a_kb_lo;
#pragma unroll
            for (int mf = 0; mf < 4; mf++) {
                int row = arow_lo + mf * 16;
                uint32_t addr = abase + row * 128 + ((akb ^ (row & 7)) << 4);
                ldsm_x4(a[mf][0], a[mf][1], a[mf][2], a[mf][3], addr);
            }
            uint32_t b[4][2];
            int bkb = 2 * ks + b_kb_lo;
#pragma unroll
            for (int nf2 = 0; nf2 < 2; nf2++) {
                int row = brow_lo + nf2 * 16;
                uint32_t addr = bbase + row * 128 + ((bkb ^ (row & 7)) << 4);
                uint32_t r0, r1, r2, r3;
                ldsm_x4(r0, r1, r2, r3, addr);
                b[nf2 * 2][0] = r0; b[nf2 * 2][1] = r1;
                b[nf2 * 2 + 1][0] = r2; b[nf2 * 2 + 1][1] = r3;
            }
#pragma unroll
            for (int mf = 0; mf < 4; mf++)
#pragma unroll
                for (int nfi = 0; nfi < 4; nfi++)
                    mma16816(acc[mf][nfi], a[mf], b[nfi]);
        }
        __syncthreads();
    }

    // ---- epilogue ----
    int g = lane >> 2, tg = lane & 3;
    const int* labC = (const int*)(smem + SM_LABC);
    const int* labR = (const int*)(smem + SM_LABR);
    unsigned* smaxr = (unsigned*)(smem + SM_MAXR);
    unsigned* smaxc = (unsigned*)(smem + SM_MAXC);

    // row-fold: masked max over this warp's 32 columns, per row
#pragma unroll
    for (int mf = 0; mf < 4; mf++) {
#pragma unroll
        for (int h = 0; h < 2; h++) {
            int row = wm * 64 + mf * 16 + g + h * 8;
            int rl = labR[row];
            float m = NEG_INF;
#pragma unroll
            for (int nfi = 0; nfi < 4; nfi++) {
                int col = wn * 32 + nfi * 8 + 2 * tg;
                if (labC[col] != rl)     m = fmaxf(m, acc[mf][nfi][h * 2 + 0]);
                if (labC[col + 1] != rl) m = fmaxf(m, acc[mf][nfi][h * 2 + 1]);
            }
            atomicMax(&smaxr[row], enc_f(m));
        }
    }

    // col-fold (mirror of symmetric tiles): masked max over this warp's 64 rows, per col
    if (colfold) {
#pragma unroll
        for (int nfi = 0; nfi < 4; nfi++) {
#pragma unroll
            for (int cpos = 0; cpos < 2; cpos++) {
                int col = wn * 32 + nfi * 8 + 2 * tg + cpos;
                int cl = labC[col];
                float m = NEG_INF;
#pragma unroll
                for (int mf = 0; mf < 4; mf++) {
#pragma unroll
                    for (int h = 0; h < 2; h++) {
                        int row = wm * 64 + mf * 16 + g + h * 8;
                        if (labR[row] != cl) m = fmaxf(m, acc[mf][nfi][h * 2 + cpos]);
                    }
                }
#pragma unroll
                for (int o = 4; o < 32; o <<= 1) m = fmaxf(m, __shfl_xor_sync(0xffffffffu, m, o));
                if (g == 0) atomicMax(&smaxc[col], enc_f(m));
            }
        }
    }

    __syncthreads();
    if (tid < TILE) {
        unsigned e = smaxr[tid];
        int grow = row0 + tid;
        if (src == 0) {
            atomicMax(&g_maxbits[0][grow], e);
            atomicMax(&g_maxbits[1][grow], e);
            if (colfold) {
                unsigned ec = smaxc[tid];
                int gcol = colbase + tid;
                atomicMax(&g_maxbits[0][gcol], ec);
                atomicMax(&g_maxbits[1][gcol], ec);
            }
        } else {
            atomicMax(&g_maxbits[src - 1][grow], e);
        }
    }
}

// ---------------- kernel 3: fused loss + reduction (single block) ----------------
__global__ void loss_kernel(float* __restrict__ out) {
    int tid = threadIdx.x;                 // 0..1023
    float s = 0.f;
#pragma unroll
    for (int k = 0; k < 8; k++) {
        int idx = tid + k * 1024;
        int v = idx >> 12;
        int i = idx & (BATCH - 1);
        float pd = g_posdot[v][i];
        float nd = dec_f(g_maxbits[v][i]);
        float pos = sqrtf(fmaxf(2.0f - 2.0f * pd, 1e-12f));
        float neg = sqrtf(fmaxf(2.0f - 2.0f * nd, 1e-12f));
        s += fmaxf(pos - neg + 1.0f, 0.0f);
    }
#pragma unroll
    for (int o = 16; o; o >>= 1) s += __shfl_down_sync(0xffffffffu, s, o);
    __shared__ float ws[32];
    if ((tid & 31) == 0) ws[tid >> 5] = s;
    __syncthreads();
    if (tid < 32) {
        float t = ws[tid];
#pragma unroll
        for (int o = 16; o; o >>= 1) t += __shfl_down_sync(0xffffffffu, t, o);
        if (tid == 0) out[0] = t * (1.0f / 8192.0f);
    }
}

// ---------------------------------------------------------------------------
extern "C" void kernel_launch(void* const* d_in, const int* in_sizes, int n_in,
                              void* d_out, int out_size) {
    const float* anchor = (const float*)d_in[0];
    const float* positive = (const float*)d_in[1];
    const int* labels = (const int*)d_in[2];

    cudaFuncSetAttribute(gemm_max_kernel, cudaFuncAttributeMaxDynamicSharedMemorySize, SM_TOTAL);

    norm_kernel<<<BATCH, 64>>>(anchor, positive);
    gemm_max_kernel<<<dim3(32, 32, 3), 256, SM_TOTAL>>>(labels);
    loss_kernel<<<1, 1024>>>((float*)d_out);
}